// round 3
// baseline (speedup 1.0000x reference)
#include <cuda_runtime.h>
#include <cuda_fp16.h>
#include <math.h>

// Problem constants: B=2, L=1024, E=1024, H=8, D=64, N_ITERS=20
#define NBH   16
#define LSEQ  1024
#define DH    64
#define EDIM  1024
#define HD    512
#define MROWS 2048
#define NITERS 20

#define NBLOCKS 148
#define MAXROWS 111      // max rows of P owned by one persistent block
// dynamic smem: P slice (MAXROWS*1024 halfs) + u (MAXROWS floats)
#define SMEM_SZ (MAXROWS * 1024 * 2 + MAXROWS * 4 + 64)

// ---------------- scratch (device globals) ----------------
__device__ float  g_q[NBH * LSEQ * DH];
__device__ float  g_k[NBH * LSEQ * DH];
__device__ float  g_v[NBH * LSEQ * DH];
__device__ __half g_P[NBH * LSEQ * LSEQ];         // 32 MB Gibbs kernel exp(logits/8)
__device__ float  g_ur[NBH * LSEQ];               // row scalings u_i
__device__ float  g_vc[NBH * LSEQ];               // col scalings v_j
__device__ float  g_attn[MROWS * HD];
__device__ float  g_cs[2][NBH * LSEQ];            // colsum double buffer
__device__ unsigned g_count = 0;                  // grid barrier state
__device__ volatile unsigned g_gen = 0;

// row partition of the 16384 global P rows over 148 blocks:
// blocks 0..103 own 111 rows, blocks 104..147 own 110 rows.
__device__ __forceinline__ int row_start(int b) {
    return (b < 104) ? b * 111 : 11544 + (b - 104) * 110;
}

// atomic grid barrier (single wave guaranteed: 148 blocks, 1/SM).
// __threadfence() = gpu-scope fence -> CCTL.IVALL, invalidates this SM's L1D.
__device__ __forceinline__ void gsync() {
    __syncthreads();
    if (threadIdx.x == 0) {
        unsigned gen = g_gen;
        __threadfence();
        if (atomicAdd(&g_count, 1u) == NBLOCKS - 1) {
            g_count = 0;
            __threadfence();
            g_gen = gen + 1;
        } else {
            while (g_gen == gen) { }
        }
        __threadfence();
    }
    __syncthreads();
}

// ============================================================================
// QKV projection: 128x128x8 register-tiled fp32 GEMM
// ============================================================================
__global__ __launch_bounds__(256) void qkv_kernel(
    const float* __restrict__ x,
    const float* __restrict__ Wq, const float* __restrict__ bq,
    const float* __restrict__ Wk, const float* __restrict__ bk,
    const float* __restrict__ Wv, const float* __restrict__ bv)
{
    const float* W; const float* bias; float* out;
    if (blockIdx.z == 0)      { W = Wq; bias = bq; out = g_q; }
    else if (blockIdx.z == 1) { W = Wk; bias = bk; out = g_k; }
    else                      { W = Wv; bias = bv; out = g_v; }

    __shared__ float As[8][132];
    __shared__ float Bs[8][132];

    const int m0 = blockIdx.y * 128;
    const int n0 = blockIdx.x * 128;
    const int tid = threadIdx.x;
    const int tx = tid & 15, ty = tid >> 4;

    const int arow = tid >> 1;
    const int akq  = (tid & 1) * 4;
    const int brow = tid >> 5;
    const int bcol = (tid & 31) * 4;

    float acc[8][8] = {};

    for (int k0 = 0; k0 < EDIM; k0 += 8) {
        float4 av = *(const float4*)(x + (m0 + arow) * EDIM + k0 + akq);
        As[akq + 0][arow] = av.x; As[akq + 1][arow] = av.y;
        As[akq + 2][arow] = av.z; As[akq + 3][arow] = av.w;
        float4 wv = *(const float4*)(W + (k0 + brow) * HD + n0 + bcol);
        *(float4*)&Bs[brow][bcol] = wv;
        __syncthreads();
        #pragma unroll
        for (int kk = 0; kk < 8; kk++) {
            float a[8], b[8];
            *(float4*)(a)     = *(float4*)&As[kk][ty * 8];
            *(float4*)(a + 4) = *(float4*)&As[kk][ty * 8 + 4];
            *(float4*)(b)     = *(float4*)&Bs[kk][tx * 8];
            *(float4*)(b + 4) = *(float4*)&Bs[kk][tx * 8 + 4];
            #pragma unroll
            for (int i = 0; i < 8; i++)
                #pragma unroll
                for (int j = 0; j < 8; j++)
                    acc[i][j] += a[i] * b[j];
        }
        __syncthreads();
    }

    #pragma unroll
    for (int i = 0; i < 8; i++) {
        int m = m0 + ty * 8 + i;
        int bb = m >> 10, l = m & 1023;
        #pragma unroll
        for (int j = 0; j < 8; j++) {
            int n = n0 + tx * 8 + j;
            int h = n >> 6, d = n & 63;
            out[(((bb << 3) + h) << 16) + (l << 6) + d] = acc[i][j] + bias[n];
        }
    }
}

// ============================================================================
// P[bh] = exp( Q K^T / 8 )  fp16.  grid (8, 8, 16)
// ============================================================================
__global__ __launch_bounds__(256) void p_kernel()
{
    __shared__ float As[8][132];
    __shared__ float Bs[8][132];

    const int bh = blockIdx.z;
    const int m0 = blockIdx.y * 128;
    const int n0 = blockIdx.x * 128;
    const int tid = threadIdx.x;
    const int tx = tid & 15, ty = tid >> 4;

    const float* Qp = g_q + bh * (LSEQ * DH);
    const float* Kp = g_k + bh * (LSEQ * DH);
    __half*      Pp = g_P + ((size_t)bh << 20);

    const int arow = tid >> 1;
    const int akq  = (tid & 1) * 4;

    float acc[8][8] = {};

    for (int k0 = 0; k0 < DH; k0 += 8) {
        float4 av = *(const float4*)(Qp + (m0 + arow) * DH + k0 + akq);
        As[akq + 0][arow] = av.x; As[akq + 1][arow] = av.y;
        As[akq + 2][arow] = av.z; As[akq + 3][arow] = av.w;
        float4 kv = *(const float4*)(Kp + (n0 + arow) * DH + k0 + akq);
        Bs[akq + 0][arow] = kv.x; Bs[akq + 1][arow] = kv.y;
        Bs[akq + 2][arow] = kv.z; Bs[akq + 3][arow] = kv.w;
        __syncthreads();
        #pragma unroll
        for (int kk = 0; kk < 8; kk++) {
            float a[8], b[8];
            *(float4*)(a)     = *(float4*)&As[kk][ty * 8];
            *(float4*)(a + 4) = *(float4*)&As[kk][ty * 8 + 4];
            *(float4*)(b)     = *(float4*)&Bs[kk][tx * 8];
            *(float4*)(b + 4) = *(float4*)&Bs[kk][tx * 8 + 4];
            #pragma unroll
            for (int i = 0; i < 8; i++)
                #pragma unroll
                for (int j = 0; j < 8; j++)
                    acc[i][j] += a[i] * b[j];
        }
        __syncthreads();
    }

    #pragma unroll
    for (int i = 0; i < 8; i++) {
        int m = m0 + ty * 8 + i;
        __half hbuf[8];
        #pragma unroll
        for (int j = 0; j < 8; j++)
            hbuf[j] = __float2half_rn(__expf(acc[i][j] * 0.125f));
        *(uint4*)(Pp + (size_t)m * LSEQ + n0 + tx * 8) = *(const uint4*)hbuf;
    }
}

// ============================================================================
// init: colsum buffer 0 = 1.0  (equivalent to v = 1)
// ============================================================================
__global__ void init_cs_kernel() {
    g_cs[0][blockIdx.x * 1024 + threadIdx.x] = 1.0f;
}

// ============================================================================
// Persistent Sinkhorn: P slice resident in SMEM, 20 iterations, grid barriers.
//   row phase: u_i = 1 / sum_j P_ij * v_j   (v_j = 1/colsumRead_j)
//   col phase: colsumWrite_j += sum_i P_ij * u_i   (atomics)
// grid 148, block 256, SMEM_SZ dynamic smem.
// ============================================================================
__global__ __launch_bounds__(256) void sinkhorn_persistent()
{
    extern __shared__ char smem_raw[];
    __half* Ps = (__half*)smem_raw;                          // [nrows][1024]
    float*  us = (float*)(smem_raw + MAXROWS * 1024 * 2);    // [nrows]

    const int b   = blockIdx.x;
    const int r0  = row_start(b);
    const int r1  = row_start(b + 1);
    const int nrows = r1 - r0;
    const int tid = threadIdx.x;
    const int warp = tid >> 5, lane = tid & 31;

    // ---- load P slice into SMEM (once) ----
    {
        const uint4* src = (const uint4*)(g_P + ((size_t)r0 << 10));
        uint4* dst = (uint4*)Ps;
        const int nvec = nrows * 1024 / 8;   // uint4 = 8 halfs
        for (int i = tid; i < nvec; i += 256) dst[i] = src[i];
    }
    __syncthreads();

    const int chunk = (nrows + 7) >> 3;       // rows per warp (contiguous)
    const int my_lo = warp * chunk;
    const int my_hi = min(nrows, my_lo + chunk);

    for (int it = 0; it < NITERS; it++) {
        const float* csR = g_cs[it & 1];
        float*       csW = g_cs[(it & 1) ^ 1];

        // zero my share of the write buffer (indices [r0, r1) of flat 16384)
        for (int i = tid; i < nrows; i += 256) csW[r0 + i] = 0.0f;

        // ---- row phase: warp per row ----
        float vr[32];
        int cur_bh = -1;
        for (int i = my_lo; i < my_hi; i++) {
            const int bh = (r0 + i) >> 10;
            if (bh != cur_bh) {
                cur_bh = bh;
                const float* cp = csR + (bh << 10);
                #pragma unroll
                for (int k = 0; k < 8; k++) {
                    float4 c4 = *(const float4*)(cp + k * 128 + lane * 4);
                    vr[k*4+0] = 1.0f / c4.x; vr[k*4+1] = 1.0f / c4.y;
                    vr[k*4+2] = 1.0f / c4.z; vr[k*4+3] = 1.0f / c4.w;
                }
            }
            const __half* Pr = Ps + (i << 10);
            float acc = 0.0f;
            #pragma unroll
            for (int k = 0; k < 8; k++) {
                uint2 pk = *(const uint2*)(Pr + k * 128 + lane * 4);
                const __half2* ph = (const __half2*)&pk;
                float2 p0 = __half22float2(ph[0]);
                float2 p1 = __half22float2(ph[1]);
                acc += p0.x * vr[k*4+0] + p0.y * vr[k*4+1]
                     + p1.x * vr[k*4+2] + p1.y * vr[k*4+3];
            }
            #pragma unroll
            for (int off = 16; off; off >>= 1)
                acc += __shfl_xor_sync(0xffffffffu, acc, off);
            if (lane == 0) us[i] = 1.0f / acc;
        }
        gsync();

        // ---- col phase: thread t owns cols 4t..4t+3, split at bh boundary ----
        {
            const int j0 = tid * 4;
            float a0 = 0, a1 = 0, a2 = 0, a3 = 0;
            int i = 0;
            int bh = r0 >> 10;
            int seg_end = min(nrows, ((bh + 1) << 10) - r0);
            #pragma unroll 1
            for (int seg = 0; seg < 2; seg++) {
                for (; i < seg_end; i++) {
                    const float u = us[i];
                    uint2 pk = *(const uint2*)(Ps + (i << 10) + j0);
                    const __half2* ph = (const __half2*)&pk;
                    float2 p0 = __half22float2(ph[0]);
                    float2 p1 = __half22float2(ph[1]);
                    a0 += p0.x * u; a1 += p0.y * u;
                    a2 += p1.x * u; a3 += p1.y * u;
                }
                float* cw = csW + (bh << 10) + j0;
                atomicAdd(cw + 0, a0); atomicAdd(cw + 1, a1);
                atomicAdd(cw + 2, a2); atomicAdd(cw + 3, a3);
                if (seg_end == nrows) break;
                a0 = a1 = a2 = a3 = 0.0f;
                bh++; seg_end = nrows;
            }
        }
        gsync();
    }

    // ---- write back u and v (final colsum is in g_cs[0]: it=19 wrote buf 0) ----
    for (int i = tid; i < nrows; i += 256) {
        g_ur[r0 + i] = us[i];
        g_vc[r0 + i] = 1.0f / g_cs[0][r0 + i];
    }
}

// ============================================================================
// out[bh] = (P .* u_i .* v_j) @ V[bh] -> g_attn.  grid (8,16), 256 thr.
// ============================================================================
__global__ __launch_bounds__(256) void attnv_kernel()
{
    __shared__ float As[8][132];
    __shared__ float Bs[8][64];

    const int bh = blockIdx.y;
    const int m0 = blockIdx.x * 128;
    const int tid = threadIdx.x;
    const int tx = tid & 15, ty = tid >> 4;

    const __half* Pp = g_P + ((size_t)bh << 20);
    const float*  Vp = g_v + bh * (LSEQ * DH);
    const float*  vp = g_vc + (bh << 10);

    const int arow = tid >> 1;
    const int akq  = (tid & 1) * 4;
    const int brow = tid >> 5;
    const int bcol = (tid & 31) * 2;

    const float u_arow = g_ur[(bh << 10) + m0 + arow];

    float acc[8][4] = {};

    for (int k0 = 0; k0 < LSEQ; k0 += 8) {
        uint2 pk = *(const uint2*)(Pp + (size_t)(m0 + arow) * LSEQ + k0 + akq);
        const __half2* ph = (const __half2*)&pk;
        float2 a01 = __half22float2(ph[0]);
        float2 a23 = __half22float2(ph[1]);
        float4 vv = *(const float4*)(vp + k0 + akq);
        As[akq + 0][arow] = a01.x * u_arow * vv.x;
        As[akq + 1][arow] = a01.y * u_arow * vv.y;
        As[akq + 2][arow] = a23.x * u_arow * vv.z;
        As[akq + 3][arow] = a23.y * u_arow * vv.w;
        float2 vv2 = *(const float2*)(Vp + (k0 + brow) * DH + bcol);
        Bs[brow][bcol]     = vv2.x;
        Bs[brow][bcol + 1] = vv2.y;
        __syncthreads();
        #pragma unroll
        for (int kk = 0; kk < 8; kk++) {
            float a[8], b[4];
            *(float4*)(a)     = *(float4*)&As[kk][ty * 8];
            *(float4*)(a + 4) = *(float4*)&As[kk][ty * 8 + 4];
            *(float4*)(b)     = *(float4*)&Bs[kk][tx * 4];
            #pragma unroll
            for (int i = 0; i < 8; i++)
                #pragma unroll
                for (int j = 0; j < 4; j++)
                    acc[i][j] += a[i] * b[j];
        }
        __syncthreads();
    }

    const int bb = bh >> 3, h = bh & 7;
    #pragma unroll
    for (int i = 0; i < 8; i++) {
        int m = m0 + ty * 8 + i;
        #pragma unroll
        for (int j = 0; j < 4; j++) {
            int n = tx * 4 + j;
            g_attn[(bb * LSEQ + m) * HD + h * DH + n] = acc[i][j];
        }
    }
}

// ============================================================================
// Output projection: d_out = g_attn(2048x512) @ Wo(512x1024) + bo. grid (8,16)
// ============================================================================
__global__ __launch_bounds__(256) void out_kernel(
    const float* __restrict__ Wo, const float* __restrict__ bo,
    float* __restrict__ out)
{
    __shared__ float As[8][132];
    __shared__ float Bs[8][132];

    const int m0 = blockIdx.y * 128;
    const int n0 = blockIdx.x * 128;
    const int tid = threadIdx.x;
    const int tx = tid & 15, ty = tid >> 4;

    const int arow = tid >> 1;
    const int akq  = (tid & 1) * 4;
    const int brow = tid >> 5;
    const int bcol = (tid & 31) * 4;

    float acc[8][8] = {};

    for (int k0 = 0; k0 < HD; k0 += 8) {
        float4 av = *(const float4*)(g_attn + (m0 + arow) * HD + k0 + akq);
        As[akq + 0][arow] = av.x; As[akq + 1][arow] = av.y;
        As[akq + 2][arow] = av.z; As[akq + 3][arow] = av.w;
        float4 wv = *(const float4*)(Wo + (k0 + brow) * EDIM + n0 + bcol);
        *(float4*)&Bs[brow][bcol] = wv;
        __syncthreads();
        #pragma unroll
        for (int kk = 0; kk < 8; kk++) {
            float a[8], b[8];
            *(float4*)(a)     = *(float4*)&As[kk][ty * 8];
            *(float4*)(a + 4) = *(float4*)&As[kk][ty * 8 + 4];
            *(float4*)(b)     = *(float4*)&Bs[kk][tx * 8];
            *(float4*)(b + 4) = *(float4*)&Bs[kk][tx * 8 + 4];
            #pragma unroll
            for (int i = 0; i < 8; i++)
                #pragma unroll
                for (int j = 0; j < 8; j++)
                    acc[i][j] += a[i] * b[j];
        }
        __syncthreads();
    }

    #pragma unroll
    for (int i = 0; i < 8; i++) {
        int m = m0 + ty * 8 + i;
        #pragma unroll
        for (int j = 0; j < 8; j++) {
            int n = n0 + tx * 8 + j;
            out[m * EDIM + n] = acc[i][j] + bo[n];
        }
    }
}

// ============================================================================
extern "C" void kernel_launch(void* const* d_in, const int* in_sizes, int n_in,
                              void* d_out, int out_size)
{
    const float* x  = (const float*)d_in[0];
    const float* Wq = (const float*)d_in[1];
    const float* bq = (const float*)d_in[2];
    const float* Wk = (const float*)d_in[3];
    const float* bk = (const float*)d_in[4];
    const float* Wv = (const float*)d_in[5];
    const float* bv = (const float*)d_in[6];
    const float* Wo = (const float*)d_in[7];
    const float* bo = (const float*)d_in[8];
    float* out = (float*)d_out;

    static int smem_set = 0;
    if (!smem_set) {
        cudaFuncSetAttribute(sinkhorn_persistent,
                             cudaFuncAttributeMaxDynamicSharedMemorySize, SMEM_SZ);
        smem_set = 1;
    }

    qkv_kernel<<<dim3(4, 16, 3), 256>>>(x, Wq, bq, Wk, bk, Wv, bv);
    p_kernel<<<dim3(8, 8, 16), 256>>>();

    init_cs_kernel<<<16, 1024>>>();
    sinkhorn_persistent<<<NBLOCKS, 256, SMEM_SZ>>>();

    attnv_kernel<<<dim3(8, NBH), 256>>>();
    out_kernel<<<dim3(8, 16), 256>>>(Wo, bo, out);
}

// round 4
// speedup vs baseline: 1.2675x; 1.2675x over previous
#include <cuda_runtime.h>
#include <cuda_fp16.h>
#include <math.h>

// Problem constants: B=2, L=1024, E=1024, H=8, D=64, N_ITERS=20
#define NBH   16
#define LSEQ  1024
#define DH    64
#define EDIM  1024
#define HD    512
#define MROWS 2048
#define NITERS 20

#define NBLOCKS 148
#define MAXROWS 111
// dynamic smem: P slice + u array (448B) + v stage / col scratch (4KB)
#define US_OFF   (MAXROWS * 1024 * 2)            // 227328
#define VS_OFF   (US_OFF + 448)                  // 227776
#define SMEM_SZ  (VS_OFF + 4096)                 // 231872 <= 232448

// ---------------- scratch (device globals) ----------------
__device__ float  g_q[NBH * LSEQ * DH];
__device__ float  g_k[NBH * LSEQ * DH];
__device__ float  g_v[NBH * LSEQ * DH];
__device__ __half g_P[NBH * LSEQ * LSEQ];         // 32 MB Gibbs kernel exp(logits/8)
__device__ float  g_ur[NBH * LSEQ];               // row scalings u_i
__device__ float  g_vc[NBH * LSEQ];               // col scalings v_j
__device__ float  g_attn[MROWS * HD];
__device__ float  g_cs3[3][NBH * LSEQ];           // colsum triple buffer
__device__ unsigned g_count = 0;
__device__ volatile unsigned g_gen = 0;

// blocks 0..103 own 111 rows, 104..147 own 110 rows (of 16384 flat P rows)
__device__ __forceinline__ int row_start(int b) {
    return (b < 104) ? b * 111 : 11544 + (b - 104) * 110;
}

// atomic grid barrier (single wave: 148 blocks, 1/SM).
__device__ __forceinline__ void gsync() {
    __syncthreads();
    if (threadIdx.x == 0) {
        unsigned gen = g_gen;
        __threadfence();
        if (atomicAdd(&g_count, 1u) == NBLOCKS - 1) {
            g_count = 0;
            __threadfence();
            g_gen = gen + 1;
        } else {
            while (g_gen == gen) { }
        }
        __threadfence();
    }
    __syncthreads();
}

// ============================================================================
// QKV projection: 128x128x8 register-tiled fp32 GEMM
// ============================================================================
__global__ __launch_bounds__(256) void qkv_kernel(
    const float* __restrict__ x,
    const float* __restrict__ Wq, const float* __restrict__ bq,
    const float* __restrict__ Wk, const float* __restrict__ bk,
    const float* __restrict__ Wv, const float* __restrict__ bv)
{
    const float* W; const float* bias; float* out;
    if (blockIdx.z == 0)      { W = Wq; bias = bq; out = g_q; }
    else if (blockIdx.z == 1) { W = Wk; bias = bk; out = g_k; }
    else                      { W = Wv; bias = bv; out = g_v; }

    __shared__ float As[8][132];
    __shared__ float Bs[8][132];

    const int m0 = blockIdx.y * 128;
    const int n0 = blockIdx.x * 128;
    const int tid = threadIdx.x;
    const int tx = tid & 15, ty = tid >> 4;

    const int arow = tid >> 1;
    const int akq  = (tid & 1) * 4;
    const int brow = tid >> 5;
    const int bcol = (tid & 31) * 4;

    float acc[8][8] = {};

    for (int k0 = 0; k0 < EDIM; k0 += 8) {
        float4 av = *(const float4*)(x + (m0 + arow) * EDIM + k0 + akq);
        As[akq + 0][arow] = av.x; As[akq + 1][arow] = av.y;
        As[akq + 2][arow] = av.z; As[akq + 3][arow] = av.w;
        float4 wv = *(const float4*)(W + (k0 + brow) * HD + n0 + bcol);
        *(float4*)&Bs[brow][bcol] = wv;
        __syncthreads();
        #pragma unroll
        for (int kk = 0; kk < 8; kk++) {
            float a[8], b[8];
            *(float4*)(a)     = *(float4*)&As[kk][ty * 8];
            *(float4*)(a + 4) = *(float4*)&As[kk][ty * 8 + 4];
            *(float4*)(b)     = *(float4*)&Bs[kk][tx * 8];
            *(float4*)(b + 4) = *(float4*)&Bs[kk][tx * 8 + 4];
            #pragma unroll
            for (int i = 0; i < 8; i++)
                #pragma unroll
                for (int j = 0; j < 8; j++)
                    acc[i][j] += a[i] * b[j];
        }
        __syncthreads();
    }

    #pragma unroll
    for (int i = 0; i < 8; i++) {
        int m = m0 + ty * 8 + i;
        int bb = m >> 10, l = m & 1023;
        #pragma unroll
        for (int j = 0; j < 8; j++) {
            int n = n0 + tx * 8 + j;
            int h = n >> 6, d = n & 63;
            out[(((bb << 3) + h) << 16) + (l << 6) + d] = acc[i][j] + bias[n];
        }
    }
}

// ============================================================================
// P[bh] = exp( Q K^T / 8 )  fp16.  grid (8, 8, 16)
// ============================================================================
__global__ __launch_bounds__(256) void p_kernel()
{
    __shared__ float As[8][132];
    __shared__ float Bs[8][132];

    const int bh = blockIdx.z;
    const int m0 = blockIdx.y * 128;
    const int n0 = blockIdx.x * 128;
    const int tid = threadIdx.x;
    const int tx = tid & 15, ty = tid >> 4;

    const float* Qp = g_q + bh * (LSEQ * DH);
    const float* Kp = g_k + bh * (LSEQ * DH);
    __half*      Pp = g_P + ((size_t)bh << 20);

    const int arow = tid >> 1;
    const int akq  = (tid & 1) * 4;

    float acc[8][8] = {};

    for (int k0 = 0; k0 < DH; k0 += 8) {
        float4 av = *(const float4*)(Qp + (m0 + arow) * DH + k0 + akq);
        As[akq + 0][arow] = av.x; As[akq + 1][arow] = av.y;
        As[akq + 2][arow] = av.z; As[akq + 3][arow] = av.w;
        float4 kv = *(const float4*)(Kp + (n0 + arow) * DH + k0 + akq);
        Bs[akq + 0][arow] = kv.x; Bs[akq + 1][arow] = kv.y;
        Bs[akq + 2][arow] = kv.z; Bs[akq + 3][arow] = kv.w;
        __syncthreads();
        #pragma unroll
        for (int kk = 0; kk < 8; kk++) {
            float a[8], b[8];
            *(float4*)(a)     = *(float4*)&As[kk][ty * 8];
            *(float4*)(a + 4) = *(float4*)&As[kk][ty * 8 + 4];
            *(float4*)(b)     = *(float4*)&Bs[kk][tx * 8];
            *(float4*)(b + 4) = *(float4*)&Bs[kk][tx * 8 + 4];
            #pragma unroll
            for (int i = 0; i < 8; i++)
                #pragma unroll
                for (int j = 0; j < 8; j++)
                    acc[i][j] += a[i] * b[j];
        }
        __syncthreads();
    }

    #pragma unroll
    for (int i = 0; i < 8; i++) {
        int m = m0 + ty * 8 + i;
        __half hbuf[8];
        #pragma unroll
        for (int j = 0; j < 8; j++)
            hbuf[j] = __float2half_rn(__expf(acc[i][j] * 0.125f));
        *(uint4*)(Pp + (size_t)m * LSEQ + n0 + tx * 8) = *(const uint4*)hbuf;
    }
}

// init: buf0 = 1 (v=1), buf1 = 0 (iter-0 write target). grid 16, block 1024.
__global__ void init_cs_kernel() {
    const int idx = blockIdx.x * 1024 + threadIdx.x;
    g_cs3[0][idx] = 1.0f;
    g_cs3[1][idx] = 0.0f;
}

// ============================================================================
// Persistent Sinkhorn v2: 1024 threads, one grid barrier per iteration,
// 3-buffer colsum rotation.  grid 148, block 1024, SMEM_SZ dynamic smem.
// ============================================================================
__global__ __launch_bounds__(1024, 1) void sinkhorn_persistent()
{
    extern __shared__ char smem_raw[];
    __half* Ps = (__half*)smem_raw;                  // [nrows][1024]
    float*  us = (float*)(smem_raw + US_OFF);        // [nrows]
    float*  vs = (float*)(smem_raw + VS_OFF);        // [1024] v stage / scratch

    const int b   = blockIdx.x;
    const int r0  = row_start(b);
    const int r1  = row_start(b + 1);
    const int nrows = r1 - r0;
    const int tid  = threadIdx.x;
    const int warp = tid >> 5, lane = tid & 31;

    // ---- load P slice into SMEM (once) ----
    {
        const uint4* src = (const uint4*)(g_P + ((size_t)r0 << 10));
        uint4* dst = (uint4*)Ps;
        const int nvec = nrows * 1024 / 8;
        for (int i = tid; i < nvec; i += 1024) dst[i] = src[i];
    }
    __syncthreads();

    const int bh_first = r0 >> 10;
    const int seg_break = min(nrows, ((bh_first + 1) << 10) - r0); // first-seg end

    for (int it = 0; it < NITERS; it++) {
        const float* csR = g_cs3[it % 3];
        float*       csW = g_cs3[(it + 1) % 3];
        float*       csZ = g_cs3[(it + 2) % 3];

        // zero next-next buffer's share (safe: nobody reads/writes it this iter)
        for (int i = tid; i < nrows; i += 1024) csZ[r0 + i] = 0.0f;

        // ================= row phase: u_i = 1 / sum_j P_ij / csR_j ==========
        int seg_lo = 0, seg_hi = seg_break, bh = bh_first;
        for (;;) {
            // stage v = 1/csR for this bh
            vs[tid] = 1.0f / csR[(bh << 10) + tid];
            __syncthreads();

            // per-warp register cache of v at this lane's positions
            float4 vr[8];
            #pragma unroll
            for (int k = 0; k < 8; k++)
                vr[k] = *(const float4*)(vs + k * 128 + lane * 4);

            for (int i = seg_lo + warp; i < seg_hi; i += 32) {
                const __half* Pr = Ps + (i << 10);
                float a0 = 0, a1 = 0, a2 = 0, a3 = 0;
                #pragma unroll
                for (int k = 0; k < 8; k++) {
                    uint2 pk = *(const uint2*)(Pr + k * 128 + lane * 4);
                    const __half2* ph = (const __half2*)&pk;
                    float2 p0 = __half22float2(ph[0]);
                    float2 p1 = __half22float2(ph[1]);
                    a0 += p0.x * vr[k].x;
                    a1 += p0.y * vr[k].y;
                    a2 += p1.x * vr[k].z;
                    a3 += p1.y * vr[k].w;
                }
                float acc = (a0 + a1) + (a2 + a3);
                #pragma unroll
                for (int off = 16; off; off >>= 1)
                    acc += __shfl_xor_sync(0xffffffffu, acc, off);
                if (lane == 0) us[i] = 1.0f / acc;
            }
            __syncthreads();   // us complete / vs reusable
            if (seg_hi == nrows) break;
            seg_lo = seg_hi; seg_hi = nrows; bh++;
        }

        // ================= col phase: csW_j += sum_i P_ij u_i ===============
        // threads: c2 = tid&511 -> cols {2c2, 2c2+1}; strip = tid>>9 (row half)
        {
            const int c2    = tid & 511;
            const int strip = tid >> 9;
            int s_lo = 0, s_hi = seg_break, bh2 = bh_first;
            for (;;) {
                const int cnt = s_hi - s_lo;
                const int mid = s_lo + ((cnt + 1) >> 1);
                const int rlo = strip ? mid : s_lo;
                const int rhi = strip ? s_hi : mid;

                float ax = 0, ay = 0;
                #pragma unroll 4
                for (int i = rlo; i < rhi; i++) {
                    const float u = us[i];
                    __half2 p = *(const __half2*)(Ps + (i << 10) + (c2 << 1));
                    float2 pf = __half22float2(p);
                    ax += pf.x * u;
                    ay += pf.y * u;
                }
                if (strip) {                    // strip1 -> scratch
                    vs[c2 * 2]     = ax;
                    vs[c2 * 2 + 1] = ay;
                }
                __syncthreads();
                if (!strip) {                   // strip0 reduces + atomics
                    ax += vs[c2 * 2];
                    ay += vs[c2 * 2 + 1];
                    float* cw = csW + (bh2 << 10) + c2 * 2;
                    atomicAdd(cw + 0, ax);
                    atomicAdd(cw + 1, ay);
                }
                __syncthreads();                // scratch reusable
                if (s_hi == nrows) break;
                s_lo = s_hi; s_hi = nrows; bh2++;
            }
        }

        gsync();   // one barrier per iteration
    }

    // final: u from smem; v = 1/colsum, colsum of iter19 lives in buf[20%3]=2
    for (int i = tid; i < nrows; i += 1024) {
        g_ur[r0 + i] = us[i];
        g_vc[r0 + i] = 1.0f / g_cs3[NITERS % 3][r0 + i];
    }
}

// ============================================================================
// out[bh] = (P .* u_i .* v_j) @ V[bh] -> g_attn.  grid (8,16), 256 thr.
// ============================================================================
__global__ __launch_bounds__(256) void attnv_kernel()
{
    __shared__ float As[8][132];
    __shared__ float Bs[8][64];

    const int bh = blockIdx.y;
    const int m0 = blockIdx.x * 128;
    const int tid = threadIdx.x;
    const int tx = tid & 15, ty = tid >> 4;

    const __half* Pp = g_P + ((size_t)bh << 20);
    const float*  Vp = g_v + bh * (LSEQ * DH);
    const float*  vp = g_vc + (bh << 10);

    const int arow = tid >> 1;
    const int akq  = (tid & 1) * 4;
    const int brow = tid >> 5;
    const int bcol = (tid & 31) * 2;

    const float u_arow = g_ur[(bh << 10) + m0 + arow];

    float acc[8][4] = {};

    for (int k0 = 0; k0 < LSEQ; k0 += 8) {
        uint2 pk = *(const uint2*)(Pp + (size_t)(m0 + arow) * LSEQ + k0 + akq);
        const __half2* ph = (const __half2*)&pk;
        float2 a01 = __half22float2(ph[0]);
        float2 a23 = __half22float2(ph[1]);
        float4 vv = *(const float4*)(vp + k0 + akq);
        As[akq + 0][arow] = a01.x * u_arow * vv.x;
        As[akq + 1][arow] = a01.y * u_arow * vv.y;
        As[akq + 2][arow] = a23.x * u_arow * vv.z;
        As[akq + 3][arow] = a23.y * u_arow * vv.w;
        float2 vv2 = *(const float2*)(Vp + (k0 + brow) * DH + bcol);
        Bs[brow][bcol]     = vv2.x;
        Bs[brow][bcol + 1] = vv2.y;
        __syncthreads();
        #pragma unroll
        for (int kk = 0; kk < 8; kk++) {
            float a[8], bv2[4];
            *(float4*)(a)     = *(float4*)&As[kk][ty * 8];
            *(float4*)(a + 4) = *(float4*)&As[kk][ty * 8 + 4];
            *(float4*)(bv2)   = *(float4*)&Bs[kk][tx * 4];
            #pragma unroll
            for (int i = 0; i < 8; i++)
                #pragma unroll
                for (int j = 0; j < 4; j++)
                    acc[i][j] += a[i] * bv2[j];
        }
        __syncthreads();
    }

    const int bb = bh >> 3, h = bh & 7;
    #pragma unroll
    for (int i = 0; i < 8; i++) {
        int m = m0 + ty * 8 + i;
        #pragma unroll
        for (int j = 0; j < 4; j++) {
            int n = tx * 4 + j;
            g_attn[(bb * LSEQ + m) * HD + h * DH + n] = acc[i][j];
        }
    }
}

// ============================================================================
// Output projection: d_out = g_attn(2048x512) @ Wo(512x1024) + bo. grid (8,16)
// ============================================================================
__global__ __launch_bounds__(256) void out_kernel(
    const float* __restrict__ Wo, const float* __restrict__ bo,
    float* __restrict__ out)
{
    __shared__ float As[8][132];
    __shared__ float Bs[8][132];

    const int m0 = blockIdx.y * 128;
    const int n0 = blockIdx.x * 128;
    const int tid = threadIdx.x;
    const int tx = tid & 15, ty = tid >> 4;

    const int arow = tid >> 1;
    const int akq  = (tid & 1) * 4;
    const int brow = tid >> 5;
    const int bcol = (tid & 31) * 4;

    float acc[8][8] = {};

    for (int k0 = 0; k0 < HD; k0 += 8) {
        float4 av = *(const float4*)(g_attn + (m0 + arow) * HD + k0 + akq);
        As[akq + 0][arow] = av.x; As[akq + 1][arow] = av.y;
        As[akq + 2][arow] = av.z; As[akq + 3][arow] = av.w;
        float4 wv = *(const float4*)(Wo + (k0 + brow) * EDIM + n0 + bcol);
        *(float4*)&Bs[brow][bcol] = wv;
        __syncthreads();
        #pragma unroll
        for (int kk = 0; kk < 8; kk++) {
            float a[8], b[8];
            *(float4*)(a)     = *(float4*)&As[kk][ty * 8];
            *(float4*)(a + 4) = *(float4*)&As[kk][ty * 8 + 4];
            *(float4*)(b)     = *(float4*)&Bs[kk][tx * 8];
            *(float4*)(b + 4) = *(float4*)&Bs[kk][tx * 8 + 4];
            #pragma unroll
            for (int i = 0; i < 8; i++)
                #pragma unroll
                for (int j = 0; j < 8; j++)
                    acc[i][j] += a[i] * b[j];
        }
        __syncthreads();
    }

    #pragma unroll
    for (int i = 0; i < 8; i++) {
        int m = m0 + ty * 8 + i;
        #pragma unroll
        for (int j = 0; j < 8; j++) {
            int n = n0 + tx * 8 + j;
            out[m * EDIM + n] = acc[i][j] + bo[n];
        }
    }
}

// ============================================================================
extern "C" void kernel_launch(void* const* d_in, const int* in_sizes, int n_in,
                              void* d_out, int out_size)
{
    const float* x  = (const float*)d_in[0];
    const float* Wq = (const float*)d_in[1];
    const float* bq = (const float*)d_in[2];
    const float* Wk = (const float*)d_in[3];
    const float* bk = (const float*)d_in[4];
    const float* Wv = (const float*)d_in[5];
    const float* bv = (const float*)d_in[6];
    const float* Wo = (const float*)d_in[7];
    const float* bo = (const float*)d_in[8];
    float* out = (float*)d_out;

    static int smem_set = 0;
    if (!smem_set) {
        cudaFuncSetAttribute(sinkhorn_persistent,
                             cudaFuncAttributeMaxDynamicSharedMemorySize, SMEM_SZ);
        smem_set = 1;
    }

    qkv_kernel<<<dim3(4, 16, 3), 256>>>(x, Wq, bq, Wk, bk, Wv, bv);
    p_kernel<<<dim3(8, 8, 16), 256>>>();

    init_cs_kernel<<<16, 1024>>>();
    sinkhorn_persistent<<<NBLOCKS, 1024, SMEM_SZ>>>();

    attnv_kernel<<<dim3(8, NBH), 256>>>();
    out_kernel<<<dim3(8, 16), 256>>>(Wo, bo, out);
}

// round 5
// speedup vs baseline: 2.5613x; 2.0208x over previous
#include <cuda_runtime.h>
#include <cuda_fp16.h>
#include <math.h>

// Problem constants: B=2, L=1024, E=1024, H=8, D=64, N_ITERS=20
#define NBH   16
#define LSEQ  1024
#define DH    64
#define EDIM  1024
#define HD    512
#define MROWS 2048
#define NITERS 20

#define NBLOCKS 148
#define MAXROWS 111
#define US_OFF   (MAXROWS * 1024 * 2)
#define VS_OFF   (US_OFF + 448)
#define SMEM_SZ  (VS_OFF + 4096)

// ---------------- scratch (device globals) ----------------
__device__ __half g_xh[MROWS * EDIM];             // x fp16 [2048][1024]
__device__ __half g_wh[3 * HD * EDIM];            // Wq/Wk/Wv^T fp16 [512][1024]
__device__ __half g_woh[EDIM * HD];               // Wo^T fp16 [1024][512]
__device__ __half g_qh[NBH * LSEQ * DH];          // Q fp16 [bh][l][d]
__device__ __half g_kh[NBH * LSEQ * DH];          // K fp16 [bh][l][d]
__device__ float  g_v [NBH * LSEQ * DH];          // V fp32 [bh][l][d]
__device__ __half g_vt[NBH * DH * LSEQ];          // (v_j*V)^T fp16 [bh][d][j]
__device__ __half g_P [NBH * LSEQ * LSEQ];        // 32 MB Gibbs kernel
__device__ __half g_ah[MROWS * HD];               // u*(P@V') fp16 [2048][512]
__device__ float  g_ur[NBH * LSEQ];
__device__ float  g_vc[NBH * LSEQ];
__device__ float  g_cs3[3][NBH * LSEQ];
__device__ unsigned g_count = 0;
__device__ volatile unsigned g_gen = 0;

// ============================================================================
// HMMA helpers
// ============================================================================
__device__ __forceinline__ void ldsm4(unsigned& r0, unsigned& r1,
                                      unsigned& r2, unsigned& r3, unsigned addr) {
    asm volatile("ldmatrix.sync.aligned.m8n8.x4.shared.b16 {%0,%1,%2,%3},[%4];\n"
                 : "=r"(r0), "=r"(r1), "=r"(r2), "=r"(r3) : "r"(addr));
}
__device__ __forceinline__ void mma16816(float* c, const unsigned* a,
                                         unsigned b0, unsigned b1) {
    asm volatile(
        "mma.sync.aligned.m16n8k16.row.col.f32.f16.f16.f32 "
        "{%0,%1,%2,%3},{%4,%5,%6,%7},{%8,%9},{%0,%1,%2,%3};\n"
        : "+f"(c[0]), "+f"(c[1]), "+f"(c[2]), "+f"(c[3])
        : "r"(a[0]), "r"(a[1]), "r"(a[2]), "r"(a[3]), "r"(b0), "r"(b1));
}

// ============================================================================
// Generic 128x64 block HMMA GEMM.  A [M][K] row-major fp16, B [N][K] fp16
// (i.e. column-major of KxN).  256 threads, warps 4(M) x 2(N), warp 32x32.
// Epi(m, n, acc) handles writeback.  K % 32 == 0.
// ============================================================================
template <class Epi>
__device__ __forceinline__ void hgemm(const __half* __restrict__ A,
                                      const __half* __restrict__ Bn,
                                      int K, int m0, int n0, Epi epi)
{
    __shared__ __half As[128 * 40];
    __shared__ __half Bs[64 * 40];

    const int tid  = threadIdx.x;
    const int lane = tid & 31, warp = tid >> 5;
    const int wm = warp & 3, wn = warp >> 2;

    const int arow = tid >> 1, acol = (tid & 1) * 16;
    const int brow = tid >> 2, bcol = (tid & 3) * 8;
    const __half* Ag = A  + (m0 + arow) * K + acol;
    const __half* Bg = Bn + (n0 + brow) * K + bcol;

    uint4 ap0 = *(const uint4*)(Ag + 0);
    uint4 ap1 = *(const uint4*)(Ag + 8);
    uint4 bp  = *(const uint4*)(Bg);

    float acc[2][4][4] = {};

    // ldmatrix source addresses (lane-dependent, k-step added in loop)
    const unsigned a_base0 = (unsigned)__cvta_generic_to_shared(
        &As[(wm * 32 + 0  + (lane & 15)) * 40 + ((lane >> 4) << 3)]);
    const unsigned a_base1 = (unsigned)__cvta_generic_to_shared(
        &As[(wm * 32 + 16 + (lane & 15)) * 40 + ((lane >> 4) << 3)]);

    for (int k0 = 0; k0 < K; k0 += 32) {
        *(uint4*)&As[arow * 40 + acol]     = ap0;
        *(uint4*)&As[arow * 40 + acol + 8] = ap1;
        *(uint4*)&Bs[brow * 40 + bcol]     = bp;
        __syncthreads();

        if (k0 + 32 < K) {
            ap0 = *(const uint4*)(Ag + k0 + 32);
            ap1 = *(const uint4*)(Ag + k0 + 40);
            bp  = *(const uint4*)(Bg + k0 + 32);
        }

        #pragma unroll
        for (int s = 0; s < 2; s++) {
            unsigned a0[4], a1[4];
            ldsm4(a0[0], a0[1], a0[2], a0[3], a_base0 + s * 32);
            ldsm4(a1[0], a1[1], a1[2], a1[3], a_base1 + s * 32);
            #pragma unroll
            for (int j = 0; j < 4; j++) {
                const __half* bh_ptr =
                    &Bs[(wn * 32 + j * 8 + (lane >> 2)) * 40 + s * 16 + (lane & 3) * 2];
                unsigned b0 = *(const unsigned*)bh_ptr;
                unsigned b1 = *(const unsigned*)(bh_ptr + 8);
                mma16816(acc[0][j], a0, b0, b1);
                mma16816(acc[1][j], a1, b0, b1);
            }
        }
        __syncthreads();
    }

    const int g = lane >> 2, c2 = (lane & 3) * 2;
    #pragma unroll
    for (int f = 0; f < 2; f++)
        #pragma unroll
        for (int j = 0; j < 4; j++) {
            int rm = m0 + wm * 32 + f * 16 + g;
            int cn = n0 + wn * 32 + j * 8 + c2;
            epi(rm,     cn,     acc[f][j][0]);
            epi(rm,     cn + 1, acc[f][j][1]);
            epi(rm + 8, cn,     acc[f][j][2]);
            epi(rm + 8, cn + 1, acc[f][j][3]);
        }
}

// ---------------- epilogues ----------------
struct EpiQKV {
    const float* bias; int z;
    __device__ void operator()(int m, int n, float v) const {
        int b = m >> 10, l = m & 1023, h = n >> 6, d = n & 63;
        int idx = (((b << 3) + h) << 16) + (l << 6) + d;
        float val = v + bias[n];
        if (z == 2)      g_v[idx]  = val;
        else if (z == 0) g_qh[idx] = __float2half_rn(val);
        else             g_kh[idx] = __float2half_rn(val);
    }
};
struct EpiP {
    __half* P;
    __device__ void operator()(int m, int n, float v) const {
        P[m * LSEQ + n] = __float2half_rn(__expf(v * 0.125f));
    }
};
struct EpiAttnV {
    int bh;
    __device__ void operator()(int m, int n, float v) const {
        float u = g_ur[(bh << 10) + m];
        int b = bh >> 3, h = bh & 7;
        g_ah[(b * LSEQ + m) * HD + h * DH + n] = __float2half_rn(u * v);
    }
};
struct EpiOut {
    const float* bo; float* out;
    __device__ void operator()(int m, int n, float v) const {
        out[m * EDIM + n] = v + bo[n];
    }
};

// ---------------- GEMM kernels ----------------
__global__ __launch_bounds__(256) void qkv_h_kernel(
    const float* __restrict__ bq, const float* __restrict__ bk,
    const float* __restrict__ bv)
{
    const int z = blockIdx.z;
    const float* bias = (z == 0) ? bq : (z == 1) ? bk : bv;
    EpiQKV epi{bias, z};
    hgemm(g_xh, g_wh + z * (HD * EDIM), EDIM,
          blockIdx.y * 128, blockIdx.x * 64, epi);
}
__global__ __launch_bounds__(256) void p_h_kernel()
{
    const int bh = blockIdx.z;
    EpiP epi{g_P + ((size_t)bh << 20)};
    hgemm(g_qh + (bh << 16), g_kh + (bh << 16), DH,
          blockIdx.y * 128, blockIdx.x * 64, epi);
}
__global__ __launch_bounds__(256) void attnv_h_kernel()
{
    const int bh = blockIdx.z;
    EpiAttnV epi{bh};
    hgemm(g_P + ((size_t)bh << 20), g_vt + (bh << 16), LSEQ,
          blockIdx.y * 128, blockIdx.x * 64, epi);
}
__global__ __launch_bounds__(256) void out_h_kernel(
    const float* __restrict__ bo, float* __restrict__ out)
{
    EpiOut epi{bo, out};
    hgemm(g_ah, g_woh, HD, blockIdx.y * 128, blockIdx.x * 64, epi);
}

// ============================================================================
// conversion kernels
// ============================================================================
__global__ void conv_x_kernel(const float* __restrict__ x) {
    int idx = blockIdx.x * 256 + threadIdx.x;     // 524288 float4s
    float4 v = ((const float4*)x)[idx];
    __half2 h0 = __floats2half2_rn(v.x, v.y);
    __half2 h1 = __floats2half2_rn(v.z, v.w);
    ((__half2*)g_xh)[2 * idx]     = h0;
    ((__half2*)g_xh)[2 * idx + 1] = h1;
}

// transpose-convert weights: z 0..2: W* [1024][512] -> g_wh[z] [512][1024];
// z == 3: Wo [512][1024] -> g_woh [1024][512].
__global__ void conv_w_kernel(const float* __restrict__ Wq,
                              const float* __restrict__ Wk,
                              const float* __restrict__ Wv,
                              const float* __restrict__ Wo)
{
    const int z = blockIdx.z;
    const float* src; __half* dst; int R, C;
    if (z < 3) { src = (z == 0) ? Wq : (z == 1) ? Wk : Wv;
                 dst = g_wh + z * (HD * EDIM); R = 1024; C = 512; }
    else       { src = Wo; dst = g_woh; R = 512; C = 1024; }
    const int r0 = blockIdx.y * 32, c0 = blockIdx.x * 32;
    if (r0 >= R || c0 >= C) return;
    __shared__ float t[32][33];
    for (int r = threadIdx.y; r < 32; r += 8)
        t[r][threadIdx.x] = src[(r0 + r) * C + c0 + threadIdx.x];
    __syncthreads();
    for (int r = threadIdx.y; r < 32; r += 8)
        dst[(c0 + r) * R + r0 + threadIdx.x] = __float2half_rn(t[threadIdx.x][r]);
}

// V'^T: g_vt[bh][d][j] = fp16( v_j * V[bh][j][d] ).  grid (32, 2, 16), (32,8)
__global__ void conv_vt_kernel()
{
    const int bh = blockIdx.z;
    const int j0 = blockIdx.x * 32, d0 = blockIdx.y * 32;
    __shared__ float t[32][33];
    for (int r = threadIdx.y; r < 32; r += 8)
        t[r][threadIdx.x] = g_v[(bh << 16) + (j0 + r) * DH + d0 + threadIdx.x];
    __syncthreads();
    for (int r = threadIdx.y; r < 32; r += 8) {
        int d = d0 + r, j = j0 + threadIdx.x;
        g_vt[(bh << 16) + (d << 10) + j] =
            __float2half_rn(g_vc[(bh << 10) + j] * t[threadIdx.x][r]);
    }
}

// ============================================================================
// Sinkhorn (unchanged from round 4)
// ============================================================================
__device__ __forceinline__ int row_start(int b) {
    return (b < 104) ? b * 111 : 11544 + (b - 104) * 110;
}
__device__ __forceinline__ void gsync() {
    __syncthreads();
    if (threadIdx.x == 0) {
        unsigned gen = g_gen;
        __threadfence();
        if (atomicAdd(&g_count, 1u) == NBLOCKS - 1) {
            g_count = 0;
            __threadfence();
            g_gen = gen + 1;
        } else {
            while (g_gen == gen) { }
        }
        __threadfence();
    }
    __syncthreads();
}

__global__ void init_cs_kernel() {
    const int idx = blockIdx.x * 1024 + threadIdx.x;
    g_cs3[0][idx] = 1.0f;
    g_cs3[1][idx] = 0.0f;
}

__global__ __launch_bounds__(1024, 1) void sinkhorn_persistent()
{
    extern __shared__ char smem_raw[];
    __half* Ps = (__half*)smem_raw;
    float*  us = (float*)(smem_raw + US_OFF);
    float*  vs = (float*)(smem_raw + VS_OFF);

    const int b   = blockIdx.x;
    const int r0  = row_start(b);
    const int r1  = row_start(b + 1);
    const int nrows = r1 - r0;
    const int tid  = threadIdx.x;
    const int warp = tid >> 5, lane = tid & 31;

    {
        const uint4* src = (const uint4*)(g_P + ((size_t)r0 << 10));
        uint4* dst = (uint4*)Ps;
        const int nvec = nrows * 1024 / 8;
        for (int i = tid; i < nvec; i += 1024) dst[i] = src[i];
    }
    __syncthreads();

    const int bh_first = r0 >> 10;
    const int seg_break = min(nrows, ((bh_first + 1) << 10) - r0);

    for (int it = 0; it < NITERS; it++) {
        const float* csR = g_cs3[it % 3];
        float*       csW = g_cs3[(it + 1) % 3];
        float*       csZ = g_cs3[(it + 2) % 3];

        for (int i = tid; i < nrows; i += 1024) csZ[r0 + i] = 0.0f;

        int seg_lo = 0, seg_hi = seg_break, bh = bh_first;
        for (;;) {
            vs[tid] = 1.0f / csR[(bh << 10) + tid];
            __syncthreads();

            float4 vr[8];
            #pragma unroll
            for (int k = 0; k < 8; k++)
                vr[k] = *(const float4*)(vs + k * 128 + lane * 4);

            for (int i = seg_lo + warp; i < seg_hi; i += 32) {
                const __half* Pr = Ps + (i << 10);
                float a0 = 0, a1 = 0, a2 = 0, a3 = 0;
                #pragma unroll
                for (int k = 0; k < 8; k++) {
                    uint2 pk = *(const uint2*)(Pr + k * 128 + lane * 4);
                    const __half2* ph = (const __half2*)&pk;
                    float2 p0 = __half22float2(ph[0]);
                    float2 p1 = __half22float2(ph[1]);
                    a0 += p0.x * vr[k].x;
                    a1 += p0.y * vr[k].y;
                    a2 += p1.x * vr[k].z;
                    a3 += p1.y * vr[k].w;
                }
                float acc = (a0 + a1) + (a2 + a3);
                #pragma unroll
                for (int off = 16; off; off >>= 1)
                    acc += __shfl_xor_sync(0xffffffffu, acc, off);
                if (lane == 0) us[i] = 1.0f / acc;
            }
            __syncthreads();
            if (seg_hi == nrows) break;
            seg_lo = seg_hi; seg_hi = nrows; bh++;
        }

        {
            const int c2    = tid & 511;
            const int strip = tid >> 9;
            int s_lo = 0, s_hi = seg_break, bh2 = bh_first;
            for (;;) {
                const int cnt = s_hi - s_lo;
                const int mid = s_lo + ((cnt + 1) >> 1);
                const int rlo = strip ? mid : s_lo;
                const int rhi = strip ? s_hi : mid;

                float ax = 0, ay = 0;
                #pragma unroll 4
                for (int i = rlo; i < rhi; i++) {
                    const float u = us[i];
                    __half2 p = *(const __half2*)(Ps + (i << 10) + (c2 << 1));
                    float2 pf = __half22float2(p);
                    ax += pf.x * u;
                    ay += pf.y * u;
                }
                if (strip) {
                    vs[c2 * 2]     = ax;
                    vs[c2 * 2 + 1] = ay;
                }
                __syncthreads();
                if (!strip) {
                    ax += vs[c2 * 2];
                    ay += vs[c2 * 2 + 1];
                    float* cw = csW + (bh2 << 10) + c2 * 2;
                    atomicAdd(cw + 0, ax);
                    atomicAdd(cw + 1, ay);
                }
                __syncthreads();
                if (s_hi == nrows) break;
                s_lo = s_hi; s_hi = nrows; bh2++;
            }
        }

        gsync();
    }

    for (int i = tid; i < nrows; i += 1024) {
        g_ur[r0 + i] = us[i];
        g_vc[r0 + i] = 1.0f / g_cs3[NITERS % 3][r0 + i];
    }
}

// ============================================================================
extern "C" void kernel_launch(void* const* d_in, const int* in_sizes, int n_in,
                              void* d_out, int out_size)
{
    const float* x  = (const float*)d_in[0];
    const float* Wq = (const float*)d_in[1];
    const float* bq = (const float*)d_in[2];
    const float* Wk = (const float*)d_in[3];
    const float* bk = (const float*)d_in[4];
    const float* Wv = (const float*)d_in[5];
    const float* bv = (const float*)d_in[6];
    const float* Wo = (const float*)d_in[7];
    const float* bo = (const float*)d_in[8];
    float* out = (float*)d_out;

    static int smem_set = 0;
    if (!smem_set) {
        cudaFuncSetAttribute(sinkhorn_persistent,
                             cudaFuncAttributeMaxDynamicSharedMemorySize, SMEM_SZ);
        smem_set = 1;
    }

    // input conversions
    conv_x_kernel<<<2048, 256>>>(x);                         // 2048*256 = 512K float4
    conv_w_kernel<<<dim3(32, 32, 4), dim3(32, 8)>>>(Wq, Wk, Wv, Wo);

    // QKV projection (fp16 tensor cores)
    qkv_h_kernel<<<dim3(8, 16, 3), 256>>>(bq, bk, bv);

    // P = exp(QK^T/8) fp16
    p_h_kernel<<<dim3(16, 8, NBH), 256>>>();

    // Sinkhorn
    init_cs_kernel<<<16, 1024>>>();
    sinkhorn_persistent<<<NBLOCKS, 1024, SMEM_SZ>>>();

    // V' = diag(v) V, transposed, fp16
    conv_vt_kernel<<<dim3(32, 2, NBH), dim3(32, 8)>>>();

    // attn @ V'  (epilogue x u_i)
    attnv_h_kernel<<<dim3(1, 8, NBH), 256>>>();

    // final projection
    out_h_kernel<<<dim3(16, 16, 1), 256>>>(bo, out);
}